// round 8
// baseline (speedup 1.0000x reference)
#include <cuda_runtime.h>
#include <math.h>

#define NAA 5
#define NCC 13
#define NPIX 361
#define MAXOBJ 50
#define NCH 130          /* NA*(13+NC) */
#define TILES 15         /* 3 x-tiles(8) * 5 y-tiles(4) */
#define BLKS_PB (NAA * TILES)   /* 75 blocks/batch: block = (anchor, tile) */

__device__ double g_accum = 0.0;
__device__ int    g_done  = 0;

__device__ __forceinline__ float sigmoidf_fast(float x) {
    return __fdividef(1.f, 1.f + __expf(-x));
}
__device__ __forceinline__ float sqrt_approx(float x) {
    float r; asm("sqrt.approx.f32 %0, %1;" : "=f"(r) : "f"(x)); return r;
}
__device__ __forceinline__ float ex2_approx(float x) {
    float r; asm("ex2.approx.f32 %0, %1;" : "=f"(r) : "f"(x)); return r;
}

#define INV_CONF0 0.15651764274966568f   /* 1/(e^2-1) */
#define EK1 (-0.036067376f)              /* -0.025 * log2(e) */
#define EK0 (2.88539008f)                /*  2.0   * log2(e) */
/* m-hat threshold: 6 + 0.4*6*(e^2-1) */
#define MHAT_TH 21.3337346f

// exact path (used only for tconf; matches reference tightly)
__device__ __forceinline__ void corner_acc(float dx, float dy, float& acc) {
    float d2 = fmaf(dy, dy, dx * dx);
    if (d2 < 6400.f)
        acc += ex2_approx(fmaf(sqrt_approx(d2), EK1, EK0)) - 1.f;
}
// branchless hot-loop path: returns e^{2-d/40} if d<80 else 1.0
// (sum over 6 corners equals the exact accumulator + 6)
__device__ __forceinline__ float corner_sel(float dx, float dy) {
    float d2 = fmaf(dy, dy, dx * dx);
    float e  = ex2_approx(fmaf(sqrt_approx(d2), EK1, EK0));
    return (d2 < 6400.f) ? e : 1.0f;
}

// grid = (75, nB), block = 128.  Block -> (anchor a, 8x4 tile t).
// Warp w handles objects w, w+4, ... ; lane = cell within tile.
__global__ void __launch_bounds__(128, 12)
fused_kernel(const float* __restrict__ out,
             const float* __restrict__ tgt,
             float* __restrict__ d_out,
             int n_blocks) {
    int b    = blockIdx.y;
    int bx   = blockIdx.x;
    int tid  = threadIdx.x;
    int w    = tid >> 5;
    int lane = tid & 31;
    int a    = bx / TILES;
    int t    = bx - a * TILES;
    bool tgt_blk = (a == 0);

    __shared__ float  stg[MAXOBJ * 15];
    __shared__ float4 s4[MAXOBJ * 3];
    __shared__ float  stv[MAXOBJ * 12];
    __shared__ float  stconf[MAXOBJ];
    __shared__ int    scls[MAXOBJ];
    __shared__ int    swin[NPIX];
    __shared__ int    snv;
    __shared__ float  spart[128];

    // ---- prep: coalesced stage + parse ----
    if (tid == 0) snv = MAXOBJ;
    if (tgt_blk)
        for (int c = tid; c < NPIX; c += 128) swin[c] = -1;
    {
        const float* src = tgt + (size_t)b * (MAXOBJ * 15);
        #pragma unroll
        for (int k = 0; k < 6; k++) {
            int idx = tid + k * 128;
            if (idx < MAXOBJ * 15) stg[idx] = src[idx];
        }
    }
    __syncthreads();

    float g[12];
    int gi = 0, gj = 0;
    if (tid < MAXOBJ) {
        const float* row = stg + tid * 15;
        #pragma unroll
        for (int k = 0; k < 12; k++) g[k] = row[1 + k];
        #pragma unroll
        for (int p = 0; p < 3; p++)
            s4[tid * 3 + p] = make_float4(g[4 * p]     * 640.f, g[4 * p + 1] * 480.f,
                                          g[4 * p + 2] * 640.f, g[4 * p + 3] * 480.f);
        if (g[0] == 0.f) atomicMin(&snv, tid);
        if (tgt_blk) {
            gi = (int)floorf(g[0] * 19.f);
            gj = (int)floorf(g[1] * 19.f);
            float* tv = stv + tid * 12;
            tv[0] = g[0] * 19.f - (float)gi;
            tv[1] = g[1] * 19.f - (float)gj;
            #pragma unroll
            for (int k = 1; k < 6; k++) {
                tv[2 * k]     = (g[2 * k]     - g[0]) * 19.f;
                tv[2 * k + 1] = (g[2 * k + 1] - g[1]) * 19.f;
            }
            scls[tid] = (int)row[0];
        }
    }
    __syncthreads();
    int nv = snv;

    // ---- winner + tconf (a==0 blocks only) ----
    if (tgt_blk && tid < nv) {
        int r = gj * 19 + gi;
        atomicMax(&swin[r], tid);

        const float* base = out + (size_t)b * NCH * NPIX + r;   // anchor 0
        float ch[12];
        #pragma unroll
        for (int c = 0; c < 12; c++) ch[c] = base[(size_t)c * NPIX];
        float x0 = sigmoidf_fast(ch[0]);
        float y0 = sigmoidf_fast(ch[1]);
        const float SX = 640.f / 19.f, SY = 480.f / 19.f;
        float px[6], py[6];
        px[0] = (x0 + (float)gi) * SX;
        py[0] = (y0 + (float)gj) * SY;
        #pragma unroll
        for (int k = 1; k < 6; k++) {
            px[k] = fmaf(ch[2 * k],     SX, px[0]);
            py[k] = fmaf(ch[2 * k + 1], SY, py[0]);
        }
        float acc = 0.f;
        #pragma unroll
        for (int c = 0; c < 6; c++)
            corner_acc(g[2 * c] * 640.f - px[c], g[2 * c + 1] * 480.f - py[c], acc);
        stconf[tid] = acc * (INV_CONF0 / 6.f);
    }
    __syncthreads();

    // ---- per-lane cell setup ----
    int tx = t % 3, ty = t / 3;
    int i = tx * 8 + (lane & 7);
    int j = ty * 4 + (lane >> 3);
    bool active = (i < 19) && (j < 19);
    int r = j * 19 + i;

    const float* base = out + ((size_t)b * NCH + a * 26) * NPIX + r;
    float ch[12];
    float x0 = 0.f, y0 = 0.f;
    float px[6], py[6];
    if (active) {
        #pragma unroll
        for (int c = 0; c < 12; c++) ch[c] = base[(size_t)c * NPIX];
        x0 = sigmoidf_fast(ch[0]);
        y0 = sigmoidf_fast(ch[1]);
        const float SX = 640.f / 19.f, SY = 480.f / 19.f;
        px[0] = (x0 + (float)i) * SX;
        py[0] = (y0 + (float)j) * SY;
        #pragma unroll
        for (int k = 1; k < 6; k++) {
            px[k] = fmaf(ch[2 * k],     SX, px[0]);
            py[k] = fmaf(ch[2 * k + 1], SY, py[0]);
        }
    } else {
        #pragma unroll
        for (int k = 0; k < 6; k++) { px[k] = 1e9f; py[k] = 1e9f; }
    }

    // ---- hot loop: branchless, warp w takes objects w, w+4, ... ----
    float m = 0.f;
    for (int q = w; q < nv; q += 4) {
        const float4* op = s4 + q * 3;
        float acc = 0.f;
        #pragma unroll
        for (int p = 0; p < 3; p++) {
            float4 v = op[p];
            acc += corner_sel(v.x - px[2 * p],     v.y - py[2 * p]);
            acc += corner_sel(v.z - px[2 * p + 1], v.w - py[2 * p + 1]);
        }
        m = fmaxf(m, acc);      // m-hat = exact acc + 6
    }
    spart[tid] = m;
    __syncthreads();

    // ---- epilogue: warp 0 only ----
    float lsum = 0.f;
    if (w == 0) {
        if (active) {
            m = fmaxf(fmaxf(spart[lane], spart[32 + lane]),
                      fmaxf(spart[64 + lane], spart[96 + lane]));

            float conf = sigmoidf_fast(base[(size_t)12 * NPIX]);
            float mask = (m < MHAT_TH) ? 1.f : 0.f;
            float tc = 0.f;

            if (tgt_blk) {
                int win = swin[r];
                if (win >= 0) {
                    mask = 5.f;   // OBJECT_SCALE
                    tc = stconf[win];

                    const float* tv = stv + win * 12;
                    float d0 = x0 - tv[0];
                    float d1 = y0 - tv[1];
                    float cs = fmaf(d1, d1, d0 * d0);
                    #pragma unroll
                    for (int k = 2; k < 12; k++) {
                        float d = ch[k] - tv[k];
                        cs = fmaf(d, d, cs);
                    }
                    lsum += 0.5f * cs;

                    const float* cbase = base + (size_t)13 * NPIX;
                    float lg[NCC];
                    float mx = -1e30f;
                    #pragma unroll
                    for (int c = 0; c < NCC; c++) {
                        lg[c] = cbase[(size_t)c * NPIX];
                        mx = fmaxf(mx, lg[c]);
                    }
                    float se = 0.f;
                    #pragma unroll
                    for (int c = 0; c < NCC; c++) se += __expf(lg[c] - mx);
                    lsum += mx + __logf(se) - lg[scls[win]];
                }
            }
            float cd = conf - tc;
            lsum += 0.5f * mask * cd * cd;
        }

        #pragma unroll
        for (int off = 16; off > 0; off >>= 1)
            lsum += __shfl_down_sync(0xffffffffu, lsum, off);
        if (lane == 0) {
            atomicAdd(&g_accum, (double)lsum);
            __threadfence();
            int old = atomicAdd(&g_done, 1);
            if (old == n_blocks - 1) {
                d_out[0] = (float)g_accum;
                g_accum = 0.0;
                g_done = 0;
            }
        }
    }
}

extern "C" void kernel_launch(void* const* d_in, const int* in_sizes, int n_in,
                              void* d_out, int out_size) {
    const float* out = (const float*)d_in[0];
    const float* tgt = (const float*)d_in[1];
    int nB = in_sizes[0] / (NCH * NPIX);

    dim3 grid(BLKS_PB, nB);
    fused_kernel<<<grid, 128>>>(out, tgt, (float*)d_out, BLKS_PB * nB);
}

// round 9
// speedup vs baseline: 1.1900x; 1.1900x over previous
#include <cuda_runtime.h>
#include <math.h>

#define NAA 5
#define NCC 13
#define NPIX 361
#define MAXOBJ 50
#define NCH 130          /* NA*(13+NC) */
#define TILES 15         /* 3 x-tiles(8) * 5 y-tiles(4) */
#define BLKS_PB (NAA * TILES)   /* 75 blocks/batch: block = (anchor, tile) */

__device__ double g_accum = 0.0;
__device__ int    g_done  = 0;

__device__ __forceinline__ float sigmoidf_fast(float x) {
    return __fdividef(1.f, 1.f + __expf(-x));
}
__device__ __forceinline__ float sqrt_approx(float x) {
    float r; asm("sqrt.approx.f32 %0, %1;" : "=f"(r) : "f"(x)); return r;
}
__device__ __forceinline__ float ex2_approx(float x) {
    float r; asm("ex2.approx.f32 %0, %1;" : "=f"(r) : "f"(x)); return r;
}

#define INV_CONF0 0.15651764274966568f   /* 1/(e^2-1) */
#define EK1 (-0.036067376f)              /* -0.025 * log2(e) */
#define EK0 (2.88539008f)                /*  2.0   * log2(e) */

// branchy corner: warp skips MUFU when no lane is within 80px (64% of the time)
__device__ __forceinline__ void corner_acc(float dx, float dy, float& acc) {
    float d2 = fmaf(dy, dy, dx * dx);
    if (d2 < 6400.f)
        acc += ex2_approx(fmaf(sqrt_approx(d2), EK1, EK0)) - 1.f;
}

// grid = (75, nB), block = 128.  Block -> (anchor a, 8x4 tile t).
// Warp w handles objects w, w+4, ... ; lane = cell within tile.
__global__ void __launch_bounds__(128, 12)
fused_kernel(const float* __restrict__ out,
             const float* __restrict__ tgt,
             float* __restrict__ d_out,
             int n_blocks) {
    int b    = blockIdx.y;
    int bx   = blockIdx.x;
    int tid  = threadIdx.x;
    int w    = tid >> 5;
    int lane = tid & 31;
    int a    = bx / TILES;
    int t    = bx - a * TILES;
    bool tgt_blk = (a == 0);

    __shared__ float  stg[MAXOBJ * 15];
    __shared__ float4 s4[MAXOBJ * 3];
    __shared__ float  stv[MAXOBJ * 12];
    __shared__ float  stconf[MAXOBJ];
    __shared__ int    scls[MAXOBJ];
    __shared__ int    swin[NPIX];
    __shared__ int    snv;
    __shared__ float  spart[128];

    // ---- prep: coalesced stage + parse ----
    if (tid == 0) snv = MAXOBJ;
    if (tgt_blk)
        for (int c = tid; c < NPIX; c += 128) swin[c] = -1;
    {
        const float* src = tgt + (size_t)b * (MAXOBJ * 15);
        #pragma unroll
        for (int k = 0; k < 6; k++) {
            int idx = tid + k * 128;
            if (idx < MAXOBJ * 15) stg[idx] = src[idx];
        }
    }
    __syncthreads();

    float g[12];
    int gi = 0, gj = 0;
    if (tid < MAXOBJ) {
        const float* row = stg + tid * 15;
        #pragma unroll
        for (int k = 0; k < 12; k++) g[k] = row[1 + k];
        #pragma unroll
        for (int p = 0; p < 3; p++)
            s4[tid * 3 + p] = make_float4(g[4 * p]     * 640.f, g[4 * p + 1] * 480.f,
                                          g[4 * p + 2] * 640.f, g[4 * p + 3] * 480.f);
        if (g[0] == 0.f) atomicMin(&snv, tid);
        if (tgt_blk) {
            gi = (int)floorf(g[0] * 19.f);
            gj = (int)floorf(g[1] * 19.f);
            float* tv = stv + tid * 12;
            tv[0] = g[0] * 19.f - (float)gi;
            tv[1] = g[1] * 19.f - (float)gj;
            #pragma unroll
            for (int k = 1; k < 6; k++) {
                tv[2 * k]     = (g[2 * k]     - g[0]) * 19.f;
                tv[2 * k + 1] = (g[2 * k + 1] - g[1]) * 19.f;
            }
            scls[tid] = (int)row[0];
        }
    }
    __syncthreads();
    int nv = snv;

    // ---- winner + tconf (a==0 blocks only) ----
    if (tgt_blk && tid < nv) {
        int r = gj * 19 + gi;
        atomicMax(&swin[r], tid);

        const float* base = out + (size_t)b * NCH * NPIX + r;   // anchor 0
        float ch[12];
        #pragma unroll
        for (int c = 0; c < 12; c++) ch[c] = base[(size_t)c * NPIX];
        float x0 = sigmoidf_fast(ch[0]);
        float y0 = sigmoidf_fast(ch[1]);
        const float SX = 640.f / 19.f, SY = 480.f / 19.f;
        float px[6], py[6];
        px[0] = (x0 + (float)gi) * SX;
        py[0] = (y0 + (float)gj) * SY;
        #pragma unroll
        for (int k = 1; k < 6; k++) {
            px[k] = fmaf(ch[2 * k],     SX, px[0]);
            py[k] = fmaf(ch[2 * k + 1], SY, py[0]);
        }
        float acc = 0.f;
        #pragma unroll
        for (int c = 0; c < 6; c++)
            corner_acc(g[2 * c] * 640.f - px[c], g[2 * c + 1] * 480.f - py[c], acc);
        stconf[tid] = acc * (INV_CONF0 / 6.f);
    }
    __syncthreads();

    // ---- per-lane cell setup ----
    int tx = t % 3, ty = t / 3;
    int i = tx * 8 + (lane & 7);
    int j = ty * 4 + (lane >> 3);
    bool active = (i < 19) && (j < 19);
    int r = j * 19 + i;

    const float* base = out + ((size_t)b * NCH + a * 26) * NPIX + r;
    float ch[12];
    float x0 = 0.f, y0 = 0.f;
    float px[6], py[6];
    if (active) {
        #pragma unroll
        for (int c = 0; c < 12; c++) ch[c] = base[(size_t)c * NPIX];
        x0 = sigmoidf_fast(ch[0]);
        y0 = sigmoidf_fast(ch[1]);
        const float SX = 640.f / 19.f, SY = 480.f / 19.f;
        px[0] = (x0 + (float)i) * SX;
        py[0] = (y0 + (float)j) * SY;
        #pragma unroll
        for (int k = 1; k < 6; k++) {
            px[k] = fmaf(ch[2 * k],     SX, px[0]);
            py[k] = fmaf(ch[2 * k + 1], SY, py[0]);
        }
    } else {
        // far away -> every corner test fails -> no MUFU, m stays 0
        #pragma unroll
        for (int k = 0; k < 6; k++) { px[k] = 1e9f; py[k] = 1e9f; }
    }

    // ---- hot loop: branchy, warp w takes objects w, w+4, ...; unroll 2 for ILP ----
    float m = 0.f;
    #pragma unroll 2
    for (int q = w; q < nv; q += 4) {
        const float4* op = s4 + q * 3;
        float acc = 0.f;
        #pragma unroll
        for (int p = 0; p < 3; p++) {
            float4 v = op[p];
            corner_acc(v.x - px[2 * p],     v.y - py[2 * p],     acc);
            corner_acc(v.z - px[2 * p + 1], v.w - py[2 * p + 1], acc);
        }
        m = fmaxf(m, acc);
    }
    spart[tid] = m;
    __syncthreads();

    // ---- epilogue: warp 0 only ----
    float lsum = 0.f;
    if (w == 0) {
        if (active) {
            m = fmaxf(fmaxf(spart[lane], spart[32 + lane]),
                      fmaxf(spart[64 + lane], spart[96 + lane]));
            m *= (INV_CONF0 / 6.f);

            float conf = sigmoidf_fast(base[(size_t)12 * NPIX]);
            float mask = (m < 0.4f) ? 1.f : 0.f;
            float tc = 0.f;

            if (tgt_blk) {
                int win = swin[r];
                if (win >= 0) {
                    mask = 5.f;   // OBJECT_SCALE
                    tc = stconf[win];

                    const float* tv = stv + win * 12;
                    float d0 = x0 - tv[0];
                    float d1 = y0 - tv[1];
                    float cs = fmaf(d1, d1, d0 * d0);
                    #pragma unroll
                    for (int k = 2; k < 12; k++) {
                        float d = ch[k] - tv[k];
                        cs = fmaf(d, d, cs);
                    }
                    lsum += 0.5f * cs;

                    const float* cbase = base + (size_t)13 * NPIX;
                    float lg[NCC];
                    float mx = -1e30f;
                    #pragma unroll
                    for (int c = 0; c < NCC; c++) {
                        lg[c] = cbase[(size_t)c * NPIX];
                        mx = fmaxf(mx, lg[c]);
                    }
                    float se = 0.f;
                    #pragma unroll
                    for (int c = 0; c < NCC; c++) se += __expf(lg[c] - mx);
                    lsum += mx + __logf(se) - lg[scls[win]];
                }
            }
            float cd = conf - tc;
            lsum += 0.5f * mask * cd * cd;
        }

        #pragma unroll
        for (int off = 16; off > 0; off >>= 1)
            lsum += __shfl_down_sync(0xffffffffu, lsum, off);
        if (lane == 0) {
            atomicAdd(&g_accum, (double)lsum);
            __threadfence();
            int old = atomicAdd(&g_done, 1);
            if (old == n_blocks - 1) {
                d_out[0] = (float)g_accum;
                g_accum = 0.0;
                g_done = 0;
            }
        }
    }
}

extern "C" void kernel_launch(void* const* d_in, const int* in_sizes, int n_in,
                              void* d_out, int out_size) {
    const float* out = (const float*)d_in[0];
    const float* tgt = (const float*)d_in[1];
    int nB = in_sizes[0] / (NCH * NPIX);

    dim3 grid(BLKS_PB, nB);
    fused_kernel<<<grid, 128>>>(out, tgt, (float*)d_out, BLKS_PB * nB);
}

// round 10
// speedup vs baseline: 1.2380x; 1.0403x over previous
#include <cuda_runtime.h>
#include <math.h>

#define NAA 5
#define NCC 13
#define NPIX 361
#define MAXOBJ 50
#define NCH 130          /* NA*(13+NC) */
#define TILES 12         /* ceil(361/32) linear 32-cell chunks */

__device__ double g_accum = 0.0;
__device__ int    g_done  = 0;

__device__ __forceinline__ float sigmoidf_fast(float x) {
    return __fdividef(1.f, 1.f + __expf(-x));
}
__device__ __forceinline__ float sqrt_approx(float x) {
    float r; asm("sqrt.approx.f32 %0, %1;" : "=f"(r) : "f"(x)); return r;
}
__device__ __forceinline__ float ex2_approx(float x) {
    float r; asm("ex2.approx.f32 %0, %1;" : "=f"(r) : "f"(x)); return r;
}

#define INV_CONF0 0.15651764274966568f   /* 1/(e^2-1) */
#define EK1 (-0.036067376f)              /* -0.025 * log2(e) */
#define EK0 (2.88539008f)                /*  2.0   * log2(e) */

// branchy corner: warp skips MUFU when no lane is within 80px
__device__ __forceinline__ void corner_acc(float dx, float dy, float& acc) {
    float d2 = fmaf(dy, dy, dx * dx);
    if (d2 < 6400.f)
        acc += ex2_approx(fmaf(sqrt_approx(d2), EK1, EK0)) - 1.f;
}

// 1D grid, heavy (a==0) blocks first: id = a*(TILES*nB) + b*TILES + t.
// Block = (anchor a, 32-cell chunk t); warp w -> objects w, w+4, ...; lane -> cell.
__global__ void __launch_bounds__(128, 12)
fused_kernel(const float* __restrict__ out,
             const float* __restrict__ tgt,
             float* __restrict__ d_out,
             int tiles_nb,        /* TILES * nB */
             int n_blocks) {
    int id   = blockIdx.x;
    int a    = id / tiles_nb;
    int rem  = id - a * tiles_nb;
    int b    = rem / TILES;
    int t    = rem - b * TILES;
    int tid  = threadIdx.x;
    int w    = tid >> 5;
    int lane = tid & 31;
    bool tgt_blk = (a == 0);

    __shared__ float  stg[MAXOBJ * 15];
    __shared__ float4 s4[MAXOBJ * 3];
    __shared__ float  stv[MAXOBJ * 12];
    __shared__ float  stconf[MAXOBJ];
    __shared__ int    scls[MAXOBJ];
    __shared__ int    swin[NPIX];
    __shared__ int    snv;
    __shared__ float  spart[128];

    // ---- prep: coalesced stage + parse ----
    if (tid == 0) snv = MAXOBJ;
    if (tgt_blk)
        for (int c = tid; c < NPIX; c += 128) swin[c] = -1;
    {
        const float* src = tgt + (size_t)b * (MAXOBJ * 15);
        #pragma unroll
        for (int k = 0; k < 6; k++) {
            int idx = tid + k * 128;
            if (idx < MAXOBJ * 15) stg[idx] = src[idx];
        }
    }
    __syncthreads();

    float g[12];
    int gi = 0, gj = 0;
    if (tid < MAXOBJ) {
        const float* row = stg + tid * 15;
        #pragma unroll
        for (int k = 0; k < 12; k++) g[k] = row[1 + k];
        #pragma unroll
        for (int p = 0; p < 3; p++)
            s4[tid * 3 + p] = make_float4(g[4 * p]     * 640.f, g[4 * p + 1] * 480.f,
                                          g[4 * p + 2] * 640.f, g[4 * p + 3] * 480.f);
        if (g[0] == 0.f) atomicMin(&snv, tid);
        if (tgt_blk) {
            gi = (int)floorf(g[0] * 19.f);
            gj = (int)floorf(g[1] * 19.f);
            float* tv = stv + tid * 12;
            tv[0] = g[0] * 19.f - (float)gi;
            tv[1] = g[1] * 19.f - (float)gj;
            #pragma unroll
            for (int k = 1; k < 6; k++) {
                tv[2 * k]     = (g[2 * k]     - g[0]) * 19.f;
                tv[2 * k + 1] = (g[2 * k + 1] - g[1]) * 19.f;
            }
            scls[tid] = (int)row[0];
        }
    }
    __syncthreads();
    int nv = snv;

    // ---- winner + tconf (a==0 blocks only) ----
    if (tgt_blk && tid < nv) {
        int r = gj * 19 + gi;
        atomicMax(&swin[r], tid);

        const float* base = out + (size_t)b * NCH * NPIX + r;   // anchor 0
        float ch[12];
        #pragma unroll
        for (int c = 0; c < 12; c++) ch[c] = base[(size_t)c * NPIX];
        float x0 = sigmoidf_fast(ch[0]);
        float y0 = sigmoidf_fast(ch[1]);
        const float SX = 640.f / 19.f, SY = 480.f / 19.f;
        float px[6], py[6];
        px[0] = (x0 + (float)gi) * SX;
        py[0] = (y0 + (float)gj) * SY;
        #pragma unroll
        for (int k = 1; k < 6; k++) {
            px[k] = fmaf(ch[2 * k],     SX, px[0]);
            py[k] = fmaf(ch[2 * k + 1], SY, py[0]);
        }
        float acc = 0.f;
        #pragma unroll
        for (int c = 0; c < 6; c++)
            corner_acc(g[2 * c] * 640.f - px[c], g[2 * c + 1] * 480.f - py[c], acc);
        stconf[tid] = acc * (INV_CONF0 / 6.f);
    }
    __syncthreads();

    // ---- per-lane cell setup: linear chunk, lane = cell ----
    int r = t * 32 + lane;
    bool active = (r < NPIX);
    int rr = active ? r : 0;
    int j = rr / 19;
    int i = rr - j * 19;

    const float* base = out + ((size_t)b * NCH + a * 26) * NPIX + rr;
    float ch[12];
    float x0 = 0.f, y0 = 0.f;
    float px[6], py[6];
    if (active) {
        #pragma unroll
        for (int c = 0; c < 12; c++) ch[c] = base[(size_t)c * NPIX];
        x0 = sigmoidf_fast(ch[0]);
        y0 = sigmoidf_fast(ch[1]);
        const float SX = 640.f / 19.f, SY = 480.f / 19.f;
        px[0] = (x0 + (float)i) * SX;
        py[0] = (y0 + (float)j) * SY;
        #pragma unroll
        for (int k = 1; k < 6; k++) {
            px[k] = fmaf(ch[2 * k],     SX, px[0]);
            py[k] = fmaf(ch[2 * k + 1], SY, py[0]);
        }
    } else {
        // far away -> every corner test fails -> no MUFU, m stays 0
        #pragma unroll
        for (int k = 0; k < 6; k++) { px[k] = 1e9f; py[k] = 1e9f; }
    }

    // ---- hot loop: branchy, warp w takes objects w, w+4, ...; unroll 2 for ILP ----
    float m = 0.f;
    #pragma unroll 2
    for (int q = w; q < nv; q += 4) {
        const float4* op = s4 + q * 3;
        float acc = 0.f;
        #pragma unroll
        for (int p = 0; p < 3; p++) {
            float4 v = op[p];
            corner_acc(v.x - px[2 * p],     v.y - py[2 * p],     acc);
            corner_acc(v.z - px[2 * p + 1], v.w - py[2 * p + 1], acc);
        }
        m = fmaxf(m, acc);
    }
    spart[tid] = m;
    __syncthreads();

    // ---- epilogue: warp 0 only ----
    float lsum = 0.f;
    if (w == 0) {
        if (active) {
            m = fmaxf(fmaxf(spart[lane], spart[32 + lane]),
                      fmaxf(spart[64 + lane], spart[96 + lane]));
            m *= (INV_CONF0 / 6.f);

            float conf = sigmoidf_fast(base[(size_t)12 * NPIX]);
            float mask = (m < 0.4f) ? 1.f : 0.f;
            float tc = 0.f;

            if (tgt_blk) {
                int win = swin[r];
                if (win >= 0) {
                    mask = 5.f;   // OBJECT_SCALE
                    tc = stconf[win];

                    const float* tv = stv + win * 12;
                    float d0 = x0 - tv[0];
                    float d1 = y0 - tv[1];
                    float cs = fmaf(d1, d1, d0 * d0);
                    #pragma unroll
                    for (int k = 2; k < 12; k++) {
                        float d = ch[k] - tv[k];
                        cs = fmaf(d, d, cs);
                    }
                    lsum += 0.5f * cs;

                    const float* cbase = base + (size_t)13 * NPIX;
                    float lg[NCC];
                    float mx = -1e30f;
                    #pragma unroll
                    for (int c = 0; c < NCC; c++) {
                        lg[c] = cbase[(size_t)c * NPIX];
                        mx = fmaxf(mx, lg[c]);
                    }
                    float se = 0.f;
                    #pragma unroll
                    for (int c = 0; c < NCC; c++) se += __expf(lg[c] - mx);
                    lsum += mx + __logf(se) - lg[scls[win]];
                }
            }
            float cd = conf - tc;
            lsum += 0.5f * mask * cd * cd;
        }

        #pragma unroll
        for (int off = 16; off > 0; off >>= 1)
            lsum += __shfl_down_sync(0xffffffffu, lsum, off);
        if (lane == 0) {
            atomicAdd(&g_accum, (double)lsum);
            __threadfence();
            int old = atomicAdd(&g_done, 1);
            if (old == n_blocks - 1) {
                d_out[0] = (float)g_accum;
                g_accum = 0.0;
                g_done = 0;
            }
        }
    }
}

extern "C" void kernel_launch(void* const* d_in, const int* in_sizes, int n_in,
                              void* d_out, int out_size) {
    const float* out = (const float*)d_in[0];
    const float* tgt = (const float*)d_in[1];
    int nB = in_sizes[0] / (NCH * NPIX);
    int tiles_nb = TILES * nB;
    int n_blocks = NAA * tiles_nb;

    fused_kernel<<<n_blocks, 128>>>(out, tgt, (float*)d_out, tiles_nb, n_blocks);
}

// round 13
// speedup vs baseline: 1.2576x; 1.0159x over previous
#include <cuda_runtime.h>
#include <math.h>

#define NAA 5
#define NCC 13
#define NPIX 361
#define MAXOBJ 50
#define NCH 130          /* NA*(13+NC) */
#define NTILE 12         /* ceil(361/32) linear 32-cell chunks */

#define SXC (640.f / 19.f)
#define SYC (480.f / 19.f)
#define INV_CONF0 0.15651764274966568f   /* 1/(e^2-1) */
#define EK1 (-0.036067376f)              /* -0.025 * log2(e) */
#define EK0 (2.88539008f)                /*  2.0   * log2(e) */

__device__ double rl_accum = 0.0;
__device__ int    rl_done  = 0;

__device__ __forceinline__ float fsigmoid(float x) {
    return __fdividef(1.f, 1.f + __expf(-x));
}
__device__ __forceinline__ float fsqrt_ap(float x) {
    float r; asm("sqrt.approx.f32 %0, %1;" : "=f"(r) : "f"(x)); return r;
}
__device__ __forceinline__ float fex2_ap(float x) {
    float r; asm("ex2.approx.f32 %0, %1;" : "=f"(r) : "f"(x)); return r;
}

// branchy corner: warp skips MUFU when no lane is within 80px
__device__ __forceinline__ void corner_acc(float dx, float dy, float& acc) {
    float d2 = fmaf(dy, dy, dx * dx);
    if (d2 < 6400.f)
        acc += fex2_ap(fmaf(fsqrt_ap(d2), EK1, EK0)) - 1.f;
}

// 1D grid, heavy (a==0) blocks first: id = a*(NTILE*nB) + b*NTILE + t.
// Block = (anchor a, 32-cell chunk t); warp w -> objects w, w+4, ...; lane -> cell.
__global__ void __launch_bounds__(128, 16)
region_loss_kernel(const float* __restrict__ out,
                   const float* __restrict__ tgt,
                   float* __restrict__ d_out,
                   int tiles_nb, int n_blocks) {
    const int id   = blockIdx.x;
    const int a    = id / tiles_nb;
    const int rem  = id - a * tiles_nb;
    const int b    = rem / NTILE;
    const int t    = rem - b * NTILE;
    const int tid  = threadIdx.x;
    const int w    = tid >> 5;
    const int lane = tid & 31;
    const bool tgt_blk = (a == 0);

    __shared__ float  stg[MAXOBJ * 15];
    __shared__ float4 s4[MAXOBJ * 3];
    __shared__ float  stv[MAXOBJ * 12];
    __shared__ float  stconf[MAXOBJ];
    __shared__ int    scls[MAXOBJ];
    __shared__ int    swin[NPIX];
    __shared__ int    snv;
    __shared__ float  spart[128];

    // ---- prep: coalesced stage of target rows ----
    if (tid == 0) snv = MAXOBJ;
    if (tgt_blk)
        for (int c = tid; c < NPIX; c += 128) swin[c] = -1;
    {
        const float* src = tgt + (size_t)b * (MAXOBJ * 15);
        #pragma unroll
        for (int k = 0; k < 6; k++) {
            int idx = tid + k * 128;
            if (idx < MAXOBJ * 15) stg[idx] = src[idx];
        }
    }
    __syncthreads();

    {   // ---- parse objects; winner + tconf (a==0 only) ----
        float g[12];
        int gi = 0, gj = 0;
        if (tid < MAXOBJ) {
            const float* row = stg + tid * 15;
            #pragma unroll
            for (int k = 0; k < 12; k++) g[k] = row[1 + k];
            #pragma unroll
            for (int p = 0; p < 3; p++)
                s4[tid * 3 + p] = make_float4(g[4 * p] * 640.f, g[4 * p + 1] * 480.f,
                                              g[4 * p + 2] * 640.f, g[4 * p + 3] * 480.f);
            if (g[0] == 0.f) atomicMin(&snv, tid);
            if (tgt_blk) {
                gi = (int)floorf(g[0] * 19.f);
                gj = (int)floorf(g[1] * 19.f);
                float* tv = stv + tid * 12;
                tv[0] = g[0] * 19.f - (float)gi;
                tv[1] = g[1] * 19.f - (float)gj;
                #pragma unroll
                for (int k = 1; k < 6; k++) {
                    tv[2 * k]     = (g[2 * k]     - g[0]) * 19.f;
                    tv[2 * k + 1] = (g[2 * k + 1] - g[1]) * 19.f;
                }
                scls[tid] = (int)row[0];
            }
        }
        __syncthreads();

        if (tgt_blk && tid < snv) {
            const int r0 = gj * 19 + gi;
            atomicMax(&swin[r0], tid);

            const float* base0 = out + (size_t)b * NCH * NPIX + r0;   // anchor 0
            float ch[12];
            #pragma unroll
            for (int c = 0; c < 12; c++) ch[c] = base0[(size_t)c * NPIX];
            float px[6], py[6];
            px[0] = (fsigmoid(ch[0]) + (float)gi) * SXC;
            py[0] = (fsigmoid(ch[1]) + (float)gj) * SYC;
            #pragma unroll
            for (int k = 1; k < 6; k++) {
                px[k] = fmaf(ch[2 * k],     SXC, px[0]);
                py[k] = fmaf(ch[2 * k + 1], SYC, py[0]);
            }
            float acc = 0.f;
            #pragma unroll
            for (int c = 0; c < 6; c++)
                corner_acc(g[2 * c] * 640.f - px[c], g[2 * c + 1] * 480.f - py[c], acc);
            stconf[tid] = acc * (INV_CONF0 / 6.f);
        }
    }
    __syncthreads();
    const int nv = snv;

    // ---- per-lane cell setup: linear chunk, lane = cell ----
    const int r = t * 32 + lane;
    const bool active = (r < NPIX);
    const int rr = active ? r : 0;
    const int j = rr / 19;
    const int i = rr - j * 19;

    const float* base = out + ((size_t)b * NCH + a * 26) * NPIX + rr;
    float px[6], py[6];
    if (active) {
        px[0] = (fsigmoid(base[0]) + (float)i) * SXC;
        py[0] = (fsigmoid(base[(size_t)1 * NPIX]) + (float)j) * SYC;
        #pragma unroll
        for (int k = 1; k < 6; k++) {
            px[k] = fmaf(base[(size_t)(2 * k)     * NPIX], SXC, px[0]);
            py[k] = fmaf(base[(size_t)(2 * k + 1) * NPIX], SYC, py[0]);
        }
    } else {
        #pragma unroll
        for (int k = 0; k < 6; k++) { px[k] = 1e9f; py[k] = 1e9f; }
    }

    // ---- hot loop: minimal live set (px/py + loop state) ----
    float m = 0.f;
    #pragma unroll 2
    for (int q = w; q < nv; q += 4) {
        const float4* op = s4 + q * 3;
        float acc = 0.f;
        #pragma unroll
        for (int p = 0; p < 3; p++) {
            float4 v = op[p];
            corner_acc(v.x - px[2 * p],     v.y - py[2 * p],     acc);
            corner_acc(v.z - px[2 * p + 1], v.w - py[2 * p + 1], acc);
        }
        m = fmaxf(m, acc);
    }
    spart[tid] = m;
    __syncthreads();

    if (w != 0) return;

    // ---- epilogue (warp 0): reload channels on the rare winner path ----
    float lsum = 0.f;
    if (active) {
        m = fmaxf(fmaxf(spart[lane], spart[32 + lane]),
                  fmaxf(spart[64 + lane], spart[96 + lane])) * (INV_CONF0 / 6.f);

        const float conf = fsigmoid(base[(size_t)12 * NPIX]);
        float mask = (m < 0.4f) ? 1.f : 0.f;
        float tc = 0.f;
        const int win = tgt_blk ? swin[r] : -1;

        if (win >= 0) {
            mask = 5.f;   // OBJECT_SCALE
            tc = stconf[win];

            float ch[12];
            #pragma unroll
            for (int c = 0; c < 12; c++) ch[c] = base[(size_t)c * NPIX];
            const float* tv = stv + win * 12;
            float d0 = fsigmoid(ch[0]) - tv[0];
            float d1 = fsigmoid(ch[1]) - tv[1];
            float cs = fmaf(d1, d1, d0 * d0);
            #pragma unroll
            for (int k = 2; k < 12; k++) {
                float d = ch[k] - tv[k];
                cs = fmaf(d, d, cs);
            }
            lsum += 0.5f * cs;

            const float* cbase = base + (size_t)13 * NPIX;
            float lg[NCC];
            float mx = -1e30f;
            #pragma unroll
            for (int c = 0; c < NCC; c++) {
                lg[c] = cbase[(size_t)c * NPIX];
                mx = fmaxf(mx, lg[c]);
            }
            float se = 0.f;
            #pragma unroll
            for (int c = 0; c < NCC; c++) se += __expf(lg[c] - mx);
            lsum += mx + __logf(se) - lg[scls[win]];
        }
        const float cd = conf - tc;
        lsum += 0.5f * mask * cd * cd;
    }

    #pragma unroll
    for (int off = 16; off > 0; off >>= 1)
        lsum += __shfl_down_sync(0xffffffffu, lsum, off);
    if (lane == 0) {
        atomicAdd(&rl_accum, (double)lsum);
        __threadfence();
        if (atomicAdd(&rl_done, 1) == n_blocks - 1) {
            d_out[0] = (float)rl_accum;
            rl_accum = 0.0;
            rl_done = 0;
        }
    }
}

extern "C" void kernel_launch(void* const* d_in, const int* in_sizes, int n_in,
                              void* d_out, int out_size) {
    const float* out = (const float*)d_in[0];
    const float* tgt = (const float*)d_in[1];
    int nB = in_sizes[0] / (NCH * NPIX);
    int tiles_nb = NTILE * nB;
    int n_blocks = NAA * tiles_nb;

    region_loss_kernel<<<n_blocks, 128>>>(out, tgt, (float*)d_out, tiles_nb, n_blocks);
}

// round 15
// speedup vs baseline: 1.3352x; 1.0617x over previous
#include <cuda_runtime.h>
#include <math.h>

#define NAA 5
#define NCC 13
#define NPIX 361
#define MAXOBJ 50
#define NCH 130          /* NA*(13+NC) */
#define NTILE 12         /* ceil(361/32) linear 32-cell chunks */

#define SXC (640.f / 19.f)
#define SYC (480.f / 19.f)
#define INV_CONF0 0.15651764274966568f   /* 1/(e^2-1) */
#define EK1 (-0.036067376f)              /* -0.025 * log2(e) */
#define EK0 (2.88539008f)                /*  2.0   * log2(e) */

__device__ double rl2_accum = 0.0;
__device__ int    rl2_done  = 0;

typedef unsigned long long u64;

__device__ __forceinline__ float fsigmoid(float x) {
    return __fdividef(1.f, 1.f + __expf(-x));
}
__device__ __forceinline__ float fsqrt_ap(float x) {
    float r; asm("sqrt.approx.f32 %0, %1;" : "=f"(r) : "f"(x)); return r;
}
__device__ __forceinline__ float fex2_ap(float x) {
    float r; asm("ex2.approx.f32 %0, %1;" : "=f"(r) : "f"(x)); return r;
}

// packed f32x2 helpers (FFMA2-class; PTX-only path, sm_100+)
__device__ __forceinline__ u64 pack2(float lo, float hi) {
    u64 r; asm("mov.b64 %0, {%1, %2};" : "=l"(r) : "f"(lo), "f"(hi)); return r;
}
__device__ __forceinline__ void unpack2(float& lo, float& hi, u64 v) {
    asm("mov.b64 {%0, %1}, %2;" : "=f"(lo), "=f"(hi) : "l"(v));
}
__device__ __forceinline__ u64 add2(u64 a, u64 b) {
    u64 r; asm("add.rn.f32x2 %0, %1, %2;" : "=l"(r) : "l"(a), "l"(b)); return r;
}
__device__ __forceinline__ u64 mul2(u64 a, u64 b) {
    u64 r; asm("mul.rn.f32x2 %0, %1, %2;" : "=l"(r) : "l"(a), "l"(b)); return r;
}
__device__ __forceinline__ u64 fma2(u64 a, u64 b, u64 c) {
    u64 r; asm("fma.rn.f32x2 %0, %1, %2, %3;" : "=l"(r) : "l"(a), "l"(b), "l"(c)); return r;
}

// scalar corner (prep/tconf path only)
__device__ __forceinline__ void corner_acc(float dx, float dy, float& acc) {
    float d2 = fmaf(dy, dy, dx * dx);
    if (d2 < 6400.f)
        acc += fex2_ap(fmaf(fsqrt_ap(d2), EK1, EK0)) - 1.f;
}
__device__ __forceinline__ void corner_d2(float d2, float& acc) {
    if (d2 < 6400.f)
        acc += fex2_ap(fmaf(fsqrt_ap(d2), EK1, EK0)) - 1.f;
}

// 1D grid, heavy (a==0) blocks first.  Block = (anchor a, 32-cell chunk t).
// Warp w -> objects w, w+4, ... ; lane -> cell.
__global__ void __launch_bounds__(128, 16)
region_loss_k14(const float* __restrict__ out,
                const float* __restrict__ tgt,
                float* __restrict__ d_out,
                int tiles_nb, int n_blocks) {
    const int id   = blockIdx.x;
    const int tid  = threadIdx.x;
    const int w    = tid >> 5;
    const int lane = tid & 31;
    const int a    = id / tiles_nb;
    const int rem  = id - a * tiles_nb;
    const int b    = rem / NTILE;
    const int t    = rem - b * NTILE;
    const bool tgt_blk = (a == 0);

    __shared__ float  stg[MAXOBJ * 15];
    __shared__ float4 s4[MAXOBJ * 3];     // (gx_{2p}, gx_{2p+1}, gy_{2p}, gy_{2p+1}) scaled
    __shared__ float  stv[MAXOBJ * 12];
    __shared__ float  stconf[MAXOBJ];
    __shared__ int    scls[MAXOBJ];
    __shared__ int    swin[NPIX];
    __shared__ int    snv;
    __shared__ float  spart[128];

    // ---- stage target rows (coalesced) ----
    if (tid == 0) snv = MAXOBJ;
    if (tgt_blk) {
        for (int c = tid; c < NPIX; c += 128) swin[c] = -1;
    }
    {
        const float* src = tgt + (size_t)b * (MAXOBJ * 15);
        #pragma unroll
        for (int k = 0; k < 6; k++) {
            const int idx = tid + k * 128;
            if (idx < MAXOBJ * 15) stg[idx] = src[idx];
        }
    }
    __syncthreads();

    // ---- parse + winner + tconf in ONE phase (validity == g0 != 0) ----
    if (tid < MAXOBJ) {
        const float* row = stg + tid * 15;
        float g[12];
        #pragma unroll
        for (int k = 0; k < 12; k++) g[k] = row[1 + k];
        // pair-major corner layout for packed math
        #pragma unroll
        for (int p = 0; p < 3; p++)
            s4[tid * 3 + p] = make_float4(g[4 * p] * 640.f, g[4 * p + 2] * 640.f,
                                          g[4 * p + 1] * 480.f, g[4 * p + 3] * 480.f);
        const bool valid = (g[0] != 0.f);
        if (!valid) atomicMin(&snv, tid);

        if (tgt_blk) {
            const int gi = (int)floorf(g[0] * 19.f);
            const int gj = (int)floorf(g[1] * 19.f);
            float* tv = stv + tid * 12;
            tv[0] = g[0] * 19.f - (float)gi;
            tv[1] = g[1] * 19.f - (float)gj;
            #pragma unroll
            for (int k = 1; k < 6; k++) {
                tv[2 * k]     = (g[2 * k]     - g[0]) * 19.f;
                tv[2 * k + 1] = (g[2 * k + 1] - g[1]) * 19.f;
            }
            scls[tid] = (int)row[0];

            if (valid) {
                const int r0 = gj * 19 + gi;
                atomicMax(&swin[r0], tid);

                const float* base0 = out + (size_t)b * NCH * NPIX + r0;  // anchor 0
                float ch[12];
                #pragma unroll
                for (int c = 0; c < 12; c++) ch[c] = base0[(size_t)c * NPIX];
                float px[6], py[6];
                px[0] = (fsigmoid(ch[0]) + (float)gi) * SXC;
                py[0] = (fsigmoid(ch[1]) + (float)gj) * SYC;
                #pragma unroll
                for (int k = 1; k < 6; k++) {
                    px[k] = fmaf(ch[2 * k],     SXC, px[0]);
                    py[k] = fmaf(ch[2 * k + 1], SYC, py[0]);
                }
                float acc = 0.f;
                #pragma unroll
                for (int c = 0; c < 6; c++)
                    corner_acc(g[2 * c] * 640.f - px[c], g[2 * c + 1] * 480.f - py[c], acc);
                stconf[tid] = acc * (INV_CONF0 / 6.f);
            }
        }
    }
    __syncthreads();
    const int nv = snv;

    // ---- per-lane cell setup ----
    const int r = t * 32 + lane;
    const bool active = (r < NPIX);
    const int rr = active ? r : 0;
    const int j = rr / 19;
    const int i = rr - j * 19;

    const float* base = out + ((size_t)b * NCH + a * 26) * NPIX + rr;
    u64 npx[3], npy[3];   // packed (-px_{2p}, -px_{2p+1}), same for y
    if (active) {
        float px[6], py[6];
        px[0] = (fsigmoid(base[0]) + (float)i) * SXC;
        py[0] = (fsigmoid(base[(size_t)1 * NPIX]) + (float)j) * SYC;
        #pragma unroll
        for (int k = 1; k < 6; k++) {
            px[k] = fmaf(base[(size_t)(2 * k)     * NPIX], SXC, px[0]);
            py[k] = fmaf(base[(size_t)(2 * k + 1) * NPIX], SYC, py[0]);
        }
        #pragma unroll
        for (int p = 0; p < 3; p++) {
            npx[p] = pack2(-px[2 * p], -px[2 * p + 1]);
            npy[p] = pack2(-py[2 * p], -py[2 * p + 1]);
        }
    } else {
        #pragma unroll
        for (int p = 0; p < 3; p++) {
            npx[p] = pack2(-1e9f, -1e9f);
            npy[p] = pack2(-1e9f, -1e9f);
        }
    }

    // ---- hot loop: packed-pair distances, branchy MUFU guard ----
    float m = 0.f;
    #pragma unroll 2
    for (int q = w; q < nv; q += 4) {
        const float4 v0 = s4[q * 3 + 0];
        const float4 v1 = s4[q * 3 + 1];
        const float4 v2 = s4[q * 3 + 2];
        float acc = 0.f;
        {
            u64 dx = add2(pack2(v0.x, v0.y), npx[0]);
            u64 dy = add2(pack2(v0.z, v0.w), npy[0]);
            u64 d2 = fma2(dy, dy, mul2(dx, dx));
            float d2a, d2b; unpack2(d2a, d2b, d2);
            corner_d2(d2a, acc); corner_d2(d2b, acc);
        }
        {
            u64 dx = add2(pack2(v1.x, v1.y), npx[1]);
            u64 dy = add2(pack2(v1.z, v1.w), npy[1]);
            u64 d2 = fma2(dy, dy, mul2(dx, dx));
            float d2a, d2b; unpack2(d2a, d2b, d2);
            corner_d2(d2a, acc); corner_d2(d2b, acc);
        }
        {
            u64 dx = add2(pack2(v2.x, v2.y), npx[2]);
            u64 dy = add2(pack2(v2.z, v2.w), npy[2]);
            u64 d2 = fma2(dy, dy, mul2(dx, dx));
            float d2a, d2b; unpack2(d2a, d2b, d2);
            corner_d2(d2a, acc); corner_d2(d2b, acc);
        }
        m = fmaxf(m, acc);
    }
    spart[tid] = m;
    __syncthreads();

    // ---- epilogue (warp 0) ----
    if (w == 0) {
        float lsum = 0.f;
        if (active) {
            m = fmaxf(fmaxf(spart[lane], spart[32 + lane]),
                      fmaxf(spart[64 + lane], spart[96 + lane])) * (INV_CONF0 / 6.f);

            const float conf = fsigmoid(base[(size_t)12 * NPIX]);
            float mask = (m < 0.4f) ? 1.f : 0.f;
            float tc = 0.f;
            const int win = tgt_blk ? swin[r] : -1;

            if (win >= 0) {
                mask = 5.f;   // OBJECT_SCALE
                tc = stconf[win];

                const float* tv = stv + win * 12;
                float d0 = fsigmoid(base[0]) - tv[0];
                float d1 = fsigmoid(base[(size_t)1 * NPIX]) - tv[1];
                float cs = fmaf(d1, d1, d0 * d0);
                #pragma unroll
                for (int k = 2; k < 12; k++) {
                    const float d = base[(size_t)k * NPIX] - tv[k];
                    cs = fmaf(d, d, cs);
                }
                lsum += 0.5f * cs;

                // two-pass log-softmax over L1-hot logits (no 13-reg array)
                const float* cbase = base + (size_t)13 * NPIX;
                float mx = -1e30f;
                #pragma unroll
                for (int c = 0; c < NCC; c++)
                    mx = fmaxf(mx, cbase[(size_t)c * NPIX]);
                float se = 0.f;
                #pragma unroll
                for (int c = 0; c < NCC; c++)
                    se += __expf(cbase[(size_t)c * NPIX] - mx);
                lsum += mx + __logf(se) - cbase[(size_t)scls[win] * NPIX];
            }
            const float cd = conf - tc;
            lsum += 0.5f * mask * cd * cd;
        }

        #pragma unroll
        for (int off = 16; off > 0; off >>= 1)
            lsum += __shfl_down_sync(0xffffffffu, lsum, off);
        if (lane == 0) {
            atomicAdd(&rl2_accum, (double)lsum);
            __threadfence();
            if (atomicAdd(&rl2_done, 1) == n_blocks - 1) {
                d_out[0] = (float)rl2_accum;
                rl2_accum = 0.0;
                rl2_done = 0;
            }
        }
    }
}

extern "C" void kernel_launch(void* const* d_in, const int* in_sizes, int n_in,
                              void* d_out, int out_size) {
    const float* out = (const float*)d_in[0];
    const float* tgt = (const float*)d_in[1];
    const int nB = in_sizes[0] / (NCH * NPIX);
    const int tiles_nb = NTILE * nB;
    const int n_blocks = NAA * tiles_nb;

    region_loss_k14<<<n_blocks, 128>>>(out, tgt, (float*)d_out, tiles_nb, n_blocks);
}

// round 17
// speedup vs baseline: 1.3523x; 1.0128x over previous
#include <cuda_runtime.h>
#include <math.h>

#define NAA 5
#define NCC 13
#define NPIX 361
#define MAXOBJ 50
#define NCH 130          /* NA*(13+NC) */
#define NTILE 12         /* ceil(361/32) linear 32-cell chunks */

#define SXC (640.f / 19.f)
#define SYC (480.f / 19.f)
#define INV_CONF0 0.15651764274966568f   /* 1/(e^2-1) */
#define EK1 (-0.036067376f)              /* -0.025 * log2(e) */
#define EK0 (2.88539008f)                /*  2.0   * log2(e) */

__device__ double rl4_sum  = 0.0;
__device__ int    rl4_cnt  = 0;

typedef unsigned long long u64;

__device__ __forceinline__ float fsigmoid(float x) {
    return __fdividef(1.f, 1.f + __expf(-x));
}
__device__ __forceinline__ float fsqrt_ap(float x) {
    float r; asm("sqrt.approx.f32 %0, %1;" : "=f"(r) : "f"(x)); return r;
}
__device__ __forceinline__ float fex2_ap(float x) {
    float r; asm("ex2.approx.f32 %0, %1;" : "=f"(r) : "f"(x)); return r;
}

// packed f32x2 helpers (sm_100+ PTX-only path)
__device__ __forceinline__ u64 pack2(float lo, float hi) {
    u64 r; asm("mov.b64 %0, {%1, %2};" : "=l"(r) : "f"(lo), "f"(hi)); return r;
}
__device__ __forceinline__ void unpack2(float& lo, float& hi, u64 v) {
    asm("mov.b64 {%0, %1}, %2;" : "=f"(lo), "=f"(hi) : "l"(v));
}
__device__ __forceinline__ u64 add2(u64 a, u64 b) {
    u64 r; asm("add.rn.f32x2 %0, %1, %2;" : "=l"(r) : "l"(a), "l"(b)); return r;
}
__device__ __forceinline__ u64 mul2(u64 a, u64 b) {
    u64 r; asm("mul.rn.f32x2 %0, %1, %2;" : "=l"(r) : "l"(a), "l"(b)); return r;
}
__device__ __forceinline__ u64 fma2(u64 a, u64 b, u64 c) {
    u64 r; asm("fma.rn.f32x2 %0, %1, %2, %3;" : "=l"(r) : "l"(a), "l"(b), "l"(c)); return r;
}

// scalar corner (prep/tconf path only)
__device__ __forceinline__ void corner_acc(float dx, float dy, float& acc) {
    float d2 = fmaf(dy, dy, dx * dx);
    if (d2 < 6400.f)
        acc += fex2_ap(fmaf(fsqrt_ap(d2), EK1, EK0)) - 1.f;
}
__device__ __forceinline__ void corner_d2(float d2, float& acc) {
    if (d2 < 6400.f)
        acc += fex2_ap(fmaf(fsqrt_ap(d2), EK1, EK0)) - 1.f;
}

// 1D grid, heavy (a==0) blocks first.  Block = (anchor a, 32-cell chunk t).
// Warp w -> objects w, w+4, ... ; lane -> cell.
__global__ void __launch_bounds__(128, 16)
region_loss_k17(const float* __restrict__ out,
                const float* __restrict__ tgt,
                float* __restrict__ d_out,
                int tiles_nb, int n_blocks) {
    const int tid  = threadIdx.x;
    const int lane = tid & 31;
    const int w    = tid >> 5;
    const int id   = blockIdx.x;
    const int a    = id / tiles_nb;
    const int rem  = id - a * tiles_nb;
    const int b    = rem / NTILE;
    const int t    = rem - b * NTILE;
    const bool tgt_blk = (a == 0);

    __shared__ float      stg[MAXOBJ * 15];
    __shared__ ulonglong2 s8[MAXOBJ * 3];   // .x = packed(gxA,gxB), .y = packed(gyA,gyB)
    __shared__ float      stv[MAXOBJ * 12];
    __shared__ float      stconf[MAXOBJ];
    __shared__ int        scls[MAXOBJ];
    __shared__ int        swin[NPIX];
    __shared__ int        snv;
    __shared__ float      spart[128];

    // ---- stage target rows (coalesced) ----
    if (tid == 0) snv = MAXOBJ;
    if (tgt_blk) {
        for (int c = tid; c < NPIX; c += 128) swin[c] = -1;
    }
    {
        const float* src = tgt + (size_t)b * (MAXOBJ * 15);
        #pragma unroll
        for (int k = 0; k < 6; k++) {
            const int idx = tid + k * 128;
            if (idx < MAXOBJ * 15) stg[idx] = src[idx];
        }
    }
    __syncthreads();

    // ---- parse + winner + tconf in ONE phase (validity == g0 != 0) ----
    if (tid < MAXOBJ) {
        const float* row = stg + tid * 15;
        float g[12];
        #pragma unroll
        for (int k = 0; k < 12; k++) g[k] = row[1 + k];
        // pair-major packed layout: low u64 = (gxA,gxB), high u64 = (gyA,gyB)
        #pragma unroll
        for (int p = 0; p < 3; p++) {
            const float4 v = make_float4(g[4 * p] * 640.f, g[4 * p + 2] * 640.f,
                                         g[4 * p + 1] * 480.f, g[4 * p + 3] * 480.f);
            *reinterpret_cast<float4*>(&s8[tid * 3 + p]) = v;
        }
        const bool valid = (g[0] != 0.f);
        if (!valid) atomicMin(&snv, tid);

        if (tgt_blk) {
            const int gi = (int)floorf(g[0] * 19.f);
            const int gj = (int)floorf(g[1] * 19.f);
            float* tv = stv + tid * 12;
            tv[0] = g[0] * 19.f - (float)gi;
            tv[1] = g[1] * 19.f - (float)gj;
            #pragma unroll
            for (int k = 1; k < 6; k++) {
                tv[2 * k]     = (g[2 * k]     - g[0]) * 19.f;
                tv[2 * k + 1] = (g[2 * k + 1] - g[1]) * 19.f;
            }
            scls[tid] = (int)row[0];

            if (valid) {
                const int r0 = gj * 19 + gi;
                atomicMax(&swin[r0], tid);

                const float* base0 = out + (size_t)b * NCH * NPIX + r0;  // anchor 0
                float ch[12];
                #pragma unroll
                for (int c = 0; c < 12; c++) ch[c] = base0[(size_t)c * NPIX];
                float px[6], py[6];
                px[0] = (fsigmoid(ch[0]) + (float)gi) * SXC;
                py[0] = (fsigmoid(ch[1]) + (float)gj) * SYC;
                #pragma unroll
                for (int k = 1; k < 6; k++) {
                    px[k] = fmaf(ch[2 * k],     SXC, px[0]);
                    py[k] = fmaf(ch[2 * k + 1], SYC, py[0]);
                }
                float acc = 0.f;
                #pragma unroll
                for (int c = 0; c < 6; c++)
                    corner_acc(g[2 * c] * 640.f - px[c], g[2 * c + 1] * 480.f - py[c], acc);
                stconf[tid] = acc * (INV_CONF0 / 6.f);
            }
        }
    }
    __syncthreads();
    const int nv = snv;

    // ---- per-lane cell setup ----
    const int r = t * 32 + lane;
    const bool active = (r < NPIX);
    const int rr = active ? r : 0;
    const int j = rr / 19;
    const int i = rr - j * 19;

    const float* base = out + ((size_t)b * NCH + a * 26) * NPIX + rr;
    u64 npx[3], npy[3];   // packed (-px_{2p}, -px_{2p+1}), same for y
    if (active) {
        float px[6], py[6];
        px[0] = (fsigmoid(base[0]) + (float)i) * SXC;
        py[0] = (fsigmoid(base[(size_t)1 * NPIX]) + (float)j) * SYC;
        #pragma unroll
        for (int k = 1; k < 6; k++) {
            px[k] = fmaf(base[(size_t)(2 * k)     * NPIX], SXC, px[0]);
            py[k] = fmaf(base[(size_t)(2 * k + 1) * NPIX], SYC, py[0]);
        }
        #pragma unroll
        for (int p = 0; p < 3; p++) {
            npx[p] = pack2(-px[2 * p], -px[2 * p + 1]);
            npy[p] = pack2(-py[2 * p], -py[2 * p + 1]);
        }
    } else {
        #pragma unroll
        for (int p = 0; p < 3; p++) {
            npx[p] = pack2(-1e9f, -1e9f);
            npy[p] = pack2(-1e9f, -1e9f);
        }
    }

    // ---- hot loop: structurally-paired f32x2 distances, branchy MUFU guard ----
    float m = 0.f;
    const ulonglong2* op = s8 + w * 3;
    #pragma unroll 2
    for (int q = w; q < nv; q += 4, op += 12) {
        float acc = 0.f;
        {
            const ulonglong2 v = op[0];
            const u64 dx = add2(v.x, npx[0]);
            const u64 dy = add2(v.y, npy[0]);
            const u64 d2 = fma2(dy, dy, mul2(dx, dx));
            float d2a, d2b; unpack2(d2a, d2b, d2);
            corner_d2(d2a, acc); corner_d2(d2b, acc);
        }
        {
            const ulonglong2 v = op[1];
            const u64 dx = add2(v.x, npx[1]);
            const u64 dy = add2(v.y, npy[1]);
            const u64 d2 = fma2(dy, dy, mul2(dx, dx));
            float d2a, d2b; unpack2(d2a, d2b, d2);
            corner_d2(d2a, acc); corner_d2(d2b, acc);
        }
        {
            const ulonglong2 v = op[2];
            const u64 dx = add2(v.x, npx[2]);
            const u64 dy = add2(v.y, npy[2]);
            const u64 d2 = fma2(dy, dy, mul2(dx, dx));
            float d2a, d2b; unpack2(d2a, d2b, d2);
            corner_d2(d2a, acc); corner_d2(d2b, acc);
        }
        m = fmaxf(m, acc);
    }
    spart[tid] = m;
    __syncthreads();

    // ---- epilogue (warp 0) ----
    if (w == 0) {
        float lsum = 0.f;
        if (active) {
            m = fmaxf(fmaxf(spart[lane], spart[32 + lane]),
                      fmaxf(spart[64 + lane], spart[96 + lane])) * (INV_CONF0 / 6.f);

            const float conf = fsigmoid(base[(size_t)12 * NPIX]);
            float mask = (m < 0.4f) ? 1.f : 0.f;
            float tc = 0.f;
            const int win = tgt_blk ? swin[r] : -1;

            if (win >= 0) {
                mask = 5.f;   // OBJECT_SCALE
                tc = stconf[win];

                const float* tv = stv + win * 12;
                const float d0 = fsigmoid(base[0]) - tv[0];
                const float d1 = fsigmoid(base[(size_t)1 * NPIX]) - tv[1];
                float cs = fmaf(d1, d1, d0 * d0);
                #pragma unroll
                for (int k = 2; k < 12; k++) {
                    const float d = base[(size_t)k * NPIX] - tv[k];
                    cs = fmaf(d, d, cs);
                }
                lsum += 0.5f * cs;

                // two-pass log-softmax over L1-hot logits (no 13-reg array)
                const float* cbase = base + (size_t)13 * NPIX;
                float mx = -1e30f;
                #pragma unroll
                for (int c = 0; c < NCC; c++)
                    mx = fmaxf(mx, cbase[(size_t)c * NPIX]);
                float se = 0.f;
                #pragma unroll
                for (int c = 0; c < NCC; c++)
                    se += __expf(cbase[(size_t)c * NPIX] - mx);
                lsum += mx + __logf(se) - cbase[(size_t)scls[win] * NPIX];
            }
            const float cd = conf - tc;
            lsum += 0.5f * mask * cd * cd;
        }

        #pragma unroll
        for (int off = 16; off > 0; off >>= 1)
            lsum += __shfl_down_sync(0xffffffffu, lsum, off);
        if (lane == 0) {
            atomicAdd(&rl4_sum, (double)lsum);
            __threadfence();
            if (atomicAdd(&rl4_cnt, 1) == n_blocks - 1) {
                d_out[0] = (float)rl4_sum;
                rl4_sum = 0.0;
                rl4_cnt = 0;
            }
        }
    }
}

extern "C" void kernel_launch(void* const* d_in, const int* in_sizes, int n_in,
                              void* d_out, int out_size) {
    const float* out = (const float*)d_in[0];
    const float* tgt = (const float*)d_in[1];
    const int nB = in_sizes[0] / (NCH * NPIX);
    const int tiles_nb = NTILE * nB;
    const int n_blocks = NAA * tiles_nb;

    region_loss_k17<<<n_blocks, 128>>>(out, tgt, (float*)d_out, tiles_nb, n_blocks);
}